// round 6
// baseline (speedup 1.0000x reference)
#include <cuda_runtime.h>
#include <cuda_bf16.h>
#include <cstdint>

// ---------------- problem constants ----------------
#define NF 128
#define NGRAPHS 10000
#define MAXM 500000
#define EPSBN 1e-5f

// ---------------- scratch globals (no allocs allowed) ----------------
__device__ float g_S[NGRAPHS * NF];
__device__ float g_P[NGRAPHS * NF];
__device__ float g_T[NGRAPHS * NF];
__device__ float g_H1[(size_t)MAXM * NF];
__device__ float g_stat0[2 * NF];            // BN0 sum/sumsq (atomics)
__device__ float g_sc0[NF], g_sh0[NF];
__device__ float g_stat1[2 * NF];            // BN1 sum/sumsq (atomics)
__device__ float g_sc1[NF], g_sh1[NF];
// weight tiles, bf16 hi/lo, layout [k][n] with pitch 136 bf16 (272B/row), 34816B
__device__ uint4 g_wlhi[2176], g_wllo[2176];
__device__ uint4 g_w1hi[2176], g_w1lo[2176], g_w2hi[2176], g_w2lo[2176];

// ---------------- smem layout (dynamic) ----------------
#define OFF_STAGE 0
#define OFF_AHI   65536
#define OFF_ALO   (65536 + 34816)
#define OFF_WHI   (65536 + 2 * 34816)
#define OFF_WLO   (65536 + 3 * 34816)
#define OFF_PRM   (65536 + 4 * 34816)
#define SMEM_MMA  (OFF_PRM + 3 * 512)   // 206,336 B

// ---------------- ptx helpers (sm_80-level only; no tcgen05!) ----------------
__device__ __forceinline__ void ldsm_x4(uint32_t* r, uint32_t addr) {
    asm volatile("ldmatrix.sync.aligned.m8n8.x4.shared.b16 {%0,%1,%2,%3}, [%4];"
                 : "=r"(r[0]), "=r"(r[1]), "=r"(r[2]), "=r"(r[3]) : "r"(addr));
}
__device__ __forceinline__ void ldsm_x4_t(uint32_t* r, uint32_t addr) {
    asm volatile("ldmatrix.sync.aligned.m8n8.x4.trans.shared.b16 {%0,%1,%2,%3}, [%4];"
                 : "=r"(r[0]), "=r"(r[1]), "=r"(r[2]), "=r"(r[3]) : "r"(addr));
}
__device__ __forceinline__ void mma_bf16(float* c, const uint32_t* a, const uint32_t* b) {
    asm volatile("mma.sync.aligned.m16n8k16.row.col.f32.bf16.bf16.f32 "
                 "{%0,%1,%2,%3}, {%4,%5,%6,%7}, {%8,%9}, {%0,%1,%2,%3};"
                 : "+f"(c[0]), "+f"(c[1]), "+f"(c[2]), "+f"(c[3])
                 : "r"(a[0]), "r"(a[1]), "r"(a[2]), "r"(a[3]), "r"(b[0]), "r"(b[1]));
}
__device__ __forceinline__ void cp16(uint32_t dst, const void* src, int sz) {
    asm volatile("cp.async.cg.shared.global [%0], [%1], 16, %2;"
                 :: "r"(dst), "l"(src), "r"(sz));
}
#define CP_COMMIT() asm volatile("cp.async.commit_group;")
#define CP_WAIT0()  asm volatile("cp.async.wait_group 0;")

// fast split: hi = truncated top-16 bits (PRMT pack), lo = rn-bf16 of residual
__device__ __forceinline__ void split4(float4 v, uint2& hi, uint2& lo) {
    uint32_t u0 = __float_as_uint(v.x), u1 = __float_as_uint(v.y),
             u2 = __float_as_uint(v.z), u3 = __float_as_uint(v.w);
    asm("prmt.b32 %0, %1, %2, 0x7632;" : "=r"(hi.x) : "r"(u0), "r"(u1));
    asm("prmt.b32 %0, %1, %2, 0x7632;" : "=r"(hi.y) : "r"(u2), "r"(u3));
    float l0 = v.x - __uint_as_float(u0 & 0xFFFF0000u);
    float l1 = v.y - __uint_as_float(u1 & 0xFFFF0000u);
    float l2 = v.z - __uint_as_float(u2 & 0xFFFF0000u);
    float l3 = v.w - __uint_as_float(u3 & 0xFFFF0000u);
    asm("cvt.rn.bf16x2.f32 %0, %1, %2;" : "=r"(lo.x) : "f"(l1), "f"(l0));
    asm("cvt.rn.bf16x2.f32 %0, %1, %2;" : "=r"(lo.y) : "f"(l3), "f"(l2));
}

// ---------------- misc small kernels ----------------
__global__ void zero_kernel() {
    const int n1 = NGRAPHS * NF;
    const int ntot = n1 + 4 * NF;
    for (int i = blockIdx.x * blockDim.x + threadIdx.x; i < ntot;
         i += gridDim.x * blockDim.x) {
        if (i < n1)               g_S[i] = 0.f;
        else if (i < n1 + 2 * NF) g_stat0[i - n1] = 0.f;
        else                      g_stat1[i - n1 - 2 * NF] = 0.f;
    }
}

// float4 lanes: 32 threads/row, 4 row-lanes, run-length accumulate per lane
__global__ void seg_sum_kernel(const float* __restrict__ x,
                               const int* __restrict__ batch, int M) {
    const int rg = threadIdx.x >> 5;   // row lane 0..3
    const int c4 = threadIdx.x & 31;   // float4 column
    int r0 = blockIdx.x * 256;
    int rend = min(r0 + 256, M);
    float4 acc = make_float4(0.f, 0.f, 0.f, 0.f);
    int cur = -1;
    for (int r = r0 + rg; r < rend; r += 4) {
        int b = __ldg(&batch[r]);
        if (b != cur) {
            if (cur >= 0) {
                float* d = &g_S[(size_t)cur * NF + c4 * 4];
                atomicAdd(d + 0, acc.x); atomicAdd(d + 1, acc.y);
                atomicAdd(d + 2, acc.z); atomicAdd(d + 3, acc.w);
            }
            acc = make_float4(0.f, 0.f, 0.f, 0.f); cur = b;
        }
        float4 v = __ldg((const float4*)x + (size_t)r * 32 + c4);
        acc.x += v.x; acc.y += v.y; acc.z += v.z; acc.w += v.w;
    }
    if (cur >= 0) {
        float* d = &g_S[(size_t)cur * NF + c4 * 4];
        atomicAdd(d + 0, acc.x); atomicAdd(d + 1, acc.y);
        atomicAdd(d + 2, acc.z); atomicAdd(d + 3, acc.w);
    }
}

__global__ void bn_prep_kernel(const float* __restrict__ sum, const float* __restrict__ ss,
                               float n, const float* __restrict__ g,
                               const float* __restrict__ b,
                               float* __restrict__ sc, float* __restrict__ sh) {
    const int c = threadIdx.x;
    float mu = sum[c] / n;
    float var = ss[c] / n - mu * mu;
    float rstd = rsqrtf(var + EPSBN);
    float s = rstd * g[c];
    sc[c] = s;
    sh[c] = b[c] - mu * s;
}

__global__ void make_T_kernel() {
    int i = blockIdx.x * blockDim.x + threadIdx.x;
    if (i < NGRAPHS * NF) {
        int c = i & (NF - 1);
        g_T[i] = fmaxf(fmaf(g_P[i], g_sc0[c], g_sh0[c]), 0.f);
    }
}

// split W_lin, W1, W2 into bf16 hi/lo tiles, layout [k][n] pitch 136 bf16
__global__ void wprep_kernel(const float* __restrict__ WL,
                             const float* __restrict__ W1,
                             const float* __restrict__ W2) {
    int i = blockIdx.x * 256 + threadIdx.x;
    if (i >= NF * NF) return;
    int k = i >> 7, n = i & 127;
    uint32_t off = (uint32_t)k * 272 + (uint32_t)n * 2;
    {
        float v = WL[i];
        __nv_bfloat16 h = __float2bfloat16(v);
        __nv_bfloat16 l = __float2bfloat16(v - __bfloat162float(h));
        *(unsigned short*)((unsigned char*)g_wlhi + off) = __bfloat16_as_ushort(h);
        *(unsigned short*)((unsigned char*)g_wllo + off) = __bfloat16_as_ushort(l);
    }
    {
        float v = W1[i];
        __nv_bfloat16 h = __float2bfloat16(v);
        __nv_bfloat16 l = __float2bfloat16(v - __bfloat162float(h));
        *(unsigned short*)((unsigned char*)g_w1hi + off) = __bfloat16_as_ushort(h);
        *(unsigned short*)((unsigned char*)g_w1lo + off) = __bfloat16_as_ushort(l);
    }
    {
        float v = W2[i];
        __nv_bfloat16 h = __float2bfloat16(v);
        __nv_bfloat16 l = __float2bfloat16(v - __bfloat162float(h));
        *(unsigned short*)((unsigned char*)g_w2hi + off) = __bfloat16_as_ushort(h);
        *(unsigned short*)((unsigned char*)g_w2lo + off) = __bfloat16_as_ushort(l);
    }
}

// ---------------- persistent HMMA (mma.sync bf16 split) GEMM ----------------
// 512 threads / 16 warps: each warp owns a 32x32 microtile of the 128x128 tile.
// MODE 0: C = Asrc @ W                       (+ fused BN0 column stats)
// MODE 1: C = (x + T[batch]) @ W + bias      (+ fused BN1 column stats)
// MODE 2: C = relu(Asrc*sc + sh) @ W + bias
template <int MODE>
__global__ void __launch_bounds__(512, 1)
gemm_mma(const float* __restrict__ Asrc,
         const uint4* __restrict__ Whi_g, const uint4* __restrict__ Wlo_g,
         const float* __restrict__ bias,
         const float* __restrict__ Tm, const int* __restrict__ batch,
         const float* __restrict__ sc, const float* __restrict__ sh,
         float* __restrict__ C, float* __restrict__ stats, int M, int ntiles) {
    constexpr bool STATS = (MODE != 2);
    constexpr bool HASBIAS = (MODE != 0);

    extern __shared__ unsigned char sm[];
    float4* stage = (float4*)(sm + OFF_STAGE);
    float*  psm   = (float*)(sm + OFF_PRM);     // bias[128], sc[128], sh[128]
    const uint32_t sb = (uint32_t)__cvta_generic_to_shared(sm);

    const int tid = threadIdx.x;
    const int wid = tid >> 5, lane = tid & 31;
    const int tig = lane & 3, grp = lane >> 2;
    const int warp_m = wid >> 2, warp_n = wid & 3;   // 4x4 warp grid, 32x32 each

    if (tid < NF) {
        psm[tid] = HASBIAS ? __ldg(&bias[tid]) : 0.f;
        if (MODE == 2) { psm[128 + tid] = __ldg(&sc[tid]); psm[256 + tid] = __ldg(&sh[tid]); }
    }
    {
        uint4* dh = (uint4*)(sm + OFF_WHI);
        uint4* dl = (uint4*)(sm + OFF_WLO);
        for (int i = tid; i < 2176; i += 512) {
            dh[i] = __ldg(&Whi_g[i]);
            dl[i] = __ldg(&Wlo_g[i]);
        }
    }

    float bias_r[4][2];
#pragma unroll
    for (int nt = 0; nt < 4; ++nt) {
        bias_r[nt][0] = HASBIAS ? __ldg(&bias[warp_n * 32 + nt * 8 + tig * 2]) : 0.f;
        bias_r[nt][1] = HASBIAS ? __ldg(&bias[warp_n * 32 + nt * 8 + tig * 2 + 1]) : 0.f;
    }

    float cs[4][2], cq[4][2];
    if (STATS) {
#pragma unroll
        for (int nt = 0; nt < 4; ++nt) { cs[nt][0] = cs[nt][1] = 0.f; cq[nt][0] = cq[nt][1] = 0.f; }
    }

    // prologue loads for first tile (4096 cp16 over 512 threads = 8 each)
    const int t0 = blockIdx.x;
    {
#pragma unroll
        for (int i = 0; i < 8; ++i) {
            int idx = tid + 512 * i;
            int r = idx >> 5, q = idx & 31;
            int rg = t0 * 128 + r;
            const float4* src = (const float4*)Asrc + (size_t)min(rg, M - 1) * 32 + q;
            uint32_t dst = sb + OFF_STAGE + (uint32_t)(r * 32 + (q ^ (r & 31))) * 16;
            cp16(dst, src, rg < M ? 16 : 0);
        }
    }
    CP_COMMIT();

    const int row_l = tid >> 2;     // convert role: row within tile (0..127)
    const int qtr   = tid & 3;      // which 32-col quarter

    for (int tile = t0; tile < ntiles; tile += gridDim.x) {
        CP_WAIT0();
        __syncthreads();

        // ---- convert stage -> Ahi/Alo (fused transform), 8 float4/thread ----
        {
            int rg = tile * 128 + row_l;
            const float4* trow = nullptr;
            if (MODE == 1) {
                int g = __ldg(&batch[min(rg, M - 1)]);
                trow = (const float4*)(Tm + (size_t)g * NF);
            }
            unsigned char* Ah = sm + OFF_AHI;
            unsigned char* Al = sm + OFF_ALO;
#pragma unroll
            for (int q = 0; q < 8; ++q) {
                int qq = qtr * 8 + q;              // float4 col idx 0..31
                float4 v = stage[row_l * 32 + (qq ^ (row_l & 31))];
                if (MODE == 1) {
                    float4 t = __ldg(trow + qq);
                    v.x += t.x; v.y += t.y; v.z += t.z; v.w += t.w;
                } else if (MODE == 2) {
                    int k0 = qq * 4;
                    v.x = fmaxf(fmaf(v.x, psm[128 + k0 + 0], psm[256 + k0 + 0]), 0.f);
                    v.y = fmaxf(fmaf(v.y, psm[128 + k0 + 1], psm[256 + k0 + 1]), 0.f);
                    v.z = fmaxf(fmaf(v.z, psm[128 + k0 + 2], psm[256 + k0 + 2]), 0.f);
                    v.w = fmaxf(fmaf(v.w, psm[128 + k0 + 3], psm[256 + k0 + 3]), 0.f);
                }
                uint2 hi, lo;
                split4(v, hi, lo);
                uint32_t off = (uint32_t)row_l * 272 + (uint32_t)qq * 8;
                *(uint2*)(Ah + off) = hi;
                *(uint2*)(Al + off) = lo;
            }
        }
        __syncthreads();

        // ---- prefetch next tile into stage ----
        {
            int nt_ = tile + gridDim.x;
            if (nt_ < ntiles) {
#pragma unroll
                for (int i = 0; i < 8; ++i) {
                    int idx = tid + 512 * i;
                    int r = idx >> 5, q = idx & 31;
                    int rg = nt_ * 128 + r;
                    const float4* src = (const float4*)Asrc + (size_t)min(rg, M - 1) * 32 + q;
                    uint32_t dst = sb + OFF_STAGE + (uint32_t)(r * 32 + (q ^ (r & 31))) * 16;
                    cp16(dst, src, rg < M ? 16 : 0);
                }
            }
            CP_COMMIT();
        }

        // ---- HMMA mainloop: 3-chain bf16 split, 32x32 microtile/warp ----
        float acc[2][4][4];
#pragma unroll
        for (int mt = 0; mt < 2; ++mt)
#pragma unroll
            for (int nt = 0; nt < 4; ++nt)
#pragma unroll
                for (int e = 0; e < 4; ++e) acc[mt][nt][e] = 0.f;

        const int lrow = lane & 15, lsel = lane >> 4;
#pragma unroll
        for (int kt = 0; kt < 8; ++kt) {
            const int k0 = kt * 16;
            uint32_t ahi[2][4], alo[2][4], whi[2][4], wlo[2][4];
#pragma unroll
            for (int mt = 0; mt < 2; ++mt) {
                int r = warp_m * 32 + mt * 16 + lrow;
                uint32_t a = sb + OFF_AHI + (uint32_t)r * 272 + (uint32_t)(k0 + lsel * 8) * 2;
                ldsm_x4(ahi[mt], a);
                ldsm_x4(alo[mt], a + (OFF_ALO - OFF_AHI));
            }
#pragma unroll
            for (int nb = 0; nb < 2; ++nb) {
                int n0 = warp_n * 32 + nb * 16;
                uint32_t a = sb + OFF_WHI + (uint32_t)(k0 + lrow) * 272 + (uint32_t)(n0 + lsel * 8) * 2;
                ldsm_x4_t(whi[nb], a);
                ldsm_x4_t(wlo[nb], a + (OFF_WLO - OFF_WHI));
            }
#pragma unroll
            for (int mt = 0; mt < 2; ++mt)
#pragma unroll
                for (int nt = 0; nt < 4; ++nt) {
                    const uint32_t* bh = &whi[nt >> 1][(nt & 1) * 2];
                    const uint32_t* bl = &wlo[nt >> 1][(nt & 1) * 2];
                    mma_bf16(acc[mt][nt], ahi[mt], bh);
                    mma_bf16(acc[mt][nt], ahi[mt], bl);
                    mma_bf16(acc[mt][nt], alo[mt], bh);
                }
        }

        // ---- epilogue: bias, store, fused stats ----
#pragma unroll
        for (int mt = 0; mt < 2; ++mt) {
            int r0 = tile * 128 + warp_m * 32 + mt * 16 + grp;
            int r1 = r0 + 8;
            bool v0 = r0 < M, v1 = r1 < M;
            float* p0 = C + (size_t)r0 * NF + warp_n * 32 + tig * 2;
            float* p1 = C + (size_t)r1 * NF + warp_n * 32 + tig * 2;
#pragma unroll
            for (int nt = 0; nt < 4; ++nt) {
                float c0 = acc[mt][nt][0] + bias_r[nt][0];
                float c1 = acc[mt][nt][1] + bias_r[nt][1];
                float c2 = acc[mt][nt][2] + bias_r[nt][0];
                float c3 = acc[mt][nt][3] + bias_r[nt][1];
                if (v0) {
                    *(float2*)(p0 + nt * 8) = make_float2(c0, c1);
                    if (STATS) { cs[nt][0] += c0; cs[nt][1] += c1; cq[nt][0] += c0 * c0; cq[nt][1] += c1 * c1; }
                }
                if (v1) {
                    *(float2*)(p1 + nt * 8) = make_float2(c2, c3);
                    if (STATS) { cs[nt][0] += c2; cs[nt][1] += c3; cq[nt][0] += c2 * c2; cq[nt][1] += c3 * c3; }
                }
            }
        }
    }

    // ---- stats flush ----
    if (STATS) {
        CP_WAIT0();         // drain any pending prologue copies into stage
        __syncthreads();    // stage now free for reuse
        float* cs_sm = (float*)(sm + OFF_STAGE);          // [16][32]
        float* cq_sm = cs_sm + 512;
#pragma unroll
        for (int nt = 0; nt < 4; ++nt)
#pragma unroll
            for (int par = 0; par < 2; ++par) {
                float s = cs[nt][par], q = cq[nt][par];
#pragma unroll
                for (int msk = 16; msk >= 4; msk >>= 1) {
                    s += __shfl_xor_sync(0xFFFFFFFFu, s, msk);
                    q += __shfl_xor_sync(0xFFFFFFFFu, q, msk);
                }
                if (lane < 4) {
                    cs_sm[wid * 32 + nt * 8 + tig * 2 + par] = s;
                    cq_sm[wid * 32 + nt * 8 + tig * 2 + par] = q;
                }
            }
        __syncthreads();
        if (tid < 128) {
            int col = tid;
            int wn = col >> 5, cl = col & 31;   // warp_n strip, col within strip
            float t = 0.f;
#pragma unroll
            for (int m = 0; m < 4; ++m) t += cs_sm[(wn + 4 * m) * 32 + cl];
            atomicAdd(&stats[col], t);
        } else if (tid < 256) {
            int col = tid - 128;
            int wn = col >> 5, cl = col & 31;
            float t = 0.f;
#pragma unroll
            for (int m = 0; m < 4; ++m) t += cq_sm[(wn + 4 * m) * 32 + cl];
            atomicAdd(&stats[NF + col], t);
        }
    }
}

// ---------------- launcher ----------------
extern "C" void kernel_launch(void* const* d_in, const int* in_sizes, int n_in,
                              void* d_out, int out_size) {
    const float* x     = (const float*)d_in[0];
    const int*   batch = (const int*)d_in[3];
    const float* W_lin = (const float*)d_in[4];
    const float* bn_g  = (const float*)d_in[5];
    const float* bn_b  = (const float*)d_in[6];
    const float* W1    = (const float*)d_in[7];
    const float* b1    = (const float*)d_in[8];
    const float* bn1_g = (const float*)d_in[9];
    const float* bn1_b = (const float*)d_in[10];
    const float* W2    = (const float*)d_in[11];
    const float* b2    = (const float*)d_in[12];
    float*       out   = (float*)d_out;

    const int M = in_sizes[0] / NF;   // 500000
    const int ntiles_big = (M + 127) / 128;
    const int ntiles_sml = (NGRAPHS + 127) / 128;   // 79

    float *pS, *pP, *pT, *pH1, *pstat0, *psc0, *psh0, *pstat1, *psc1, *psh1;
    cudaGetSymbolAddress((void**)&pS, g_S);
    cudaGetSymbolAddress((void**)&pP, g_P);
    cudaGetSymbolAddress((void**)&pT, g_T);
    cudaGetSymbolAddress((void**)&pH1, g_H1);
    cudaGetSymbolAddress((void**)&pstat0, g_stat0);
    cudaGetSymbolAddress((void**)&psc0, g_sc0);
    cudaGetSymbolAddress((void**)&psh0, g_sh0);
    cudaGetSymbolAddress((void**)&pstat1, g_stat1);
    cudaGetSymbolAddress((void**)&psc1, g_sc1);
    cudaGetSymbolAddress((void**)&psh1, g_sh1);
    uint4 *pwlh, *pwll, *pw1h, *pw1l, *pw2h, *pw2l;
    cudaGetSymbolAddress((void**)&pwlh, g_wlhi);
    cudaGetSymbolAddress((void**)&pwll, g_wllo);
    cudaGetSymbolAddress((void**)&pw1h, g_w1hi);
    cudaGetSymbolAddress((void**)&pw1l, g_w1lo);
    cudaGetSymbolAddress((void**)&pw2h, g_w2hi);
    cudaGetSymbolAddress((void**)&pw2l, g_w2lo);

    int dev = 0, nsm = 148;
    cudaGetDevice(&dev);
    cudaDeviceGetAttribute(&nsm, cudaDevAttrMultiProcessorCount, dev);

    cudaFuncSetAttribute(gemm_mma<0>, cudaFuncAttributeMaxDynamicSharedMemorySize, SMEM_MMA);
    cudaFuncSetAttribute(gemm_mma<1>, cudaFuncAttributeMaxDynamicSharedMemorySize, SMEM_MMA);
    cudaFuncSetAttribute(gemm_mma<2>, cudaFuncAttributeMaxDynamicSharedMemorySize, SMEM_MMA);

    // 1) zero accumulators; split+layout weights
    zero_kernel<<<2500, 256>>>();
    wprep_kernel<<<(NF * NF + 255) / 256, 256>>>(W_lin, W1, W2);
    // 2) segment sum
    seg_sum_kernel<<<(M + 255) / 256, 128>>>(x, batch, M);
    // 3) P = S @ W_lin  (HMMA, fused BN0 stats)
    gemm_mma<0><<<nsm, 512, SMEM_MMA>>>(pS, pwlh, pwll, nullptr, nullptr, nullptr,
                                        nullptr, nullptr, pP, pstat0, NGRAPHS, ntiles_sml);
    // 4) BN0 scale/shift, T = relu(BN(P))
    bn_prep_kernel<<<1, NF>>>(pstat0, pstat0 + NF, (float)NGRAPHS, bn_g, bn_b, psc0, psh0);
    make_T_kernel<<<(NGRAPHS * NF + 255) / 256, 256>>>();
    // 5) H1 = (x + T[batch]) @ W1 + b1  (HMMA, fused BN1 stats)
    gemm_mma<1><<<nsm, 512, SMEM_MMA>>>(x, pw1h, pw1l, b1, pT, batch,
                                        nullptr, nullptr, pH1, pstat1, M, ntiles_big);
    // 6) BN1 scale/shift
    bn_prep_kernel<<<1, NF>>>(pstat1, pstat1 + NF, (float)M, bn1_g, bn1_b, psc1, psh1);
    // 7) out = relu(BN(H1)) @ W2 + b2  (HMMA)
    gemm_mma<2><<<nsm, 512, SMEM_MMA>>>(pH1, pw2h, pw2l, b2, nullptr, nullptr,
                                        psc1, psh1, out, nullptr, M, ntiles_big);
}

// round 7
// speedup vs baseline: 1.0086x; 1.0086x over previous
#include <cuda_runtime.h>
#include <cuda_bf16.h>
#include <cstdint>

// ---------------- problem constants ----------------
#define NF 128
#define NGRAPHS 10000
#define MAXM 500000
#define EPSBN 1e-5f

// ---------------- scratch globals (no allocs allowed) ----------------
__device__ float g_S[NGRAPHS * NF];
__device__ float g_P[NGRAPHS * NF];
__device__ float g_T[NGRAPHS * NF];
__device__ float g_H1[(size_t)MAXM * NF];
__device__ float g_stat0[2 * NF];            // BN0 sum/sumsq (atomics)
__device__ float g_sc0[NF], g_sh0[NF];
__device__ float g_stat1[2 * NF];            // BN1 sum/sumsq (atomics)
__device__ float g_sc1[NF], g_sh1[NF];
// weight tiles, bf16 hi/lo, layout [k][n] with pitch 136 bf16 (272B/row), 34816B
__device__ uint4 g_wlhi[2176], g_wllo[2176];
__device__ uint4 g_w1hi[2176], g_w1lo[2176], g_w2hi[2176], g_w2lo[2176];

// ---------------- smem layout (dynamic) ----------------
// A buffers: [hi 34816][lo 34816] x2, double-buffered; W hi/lo; params
#define OFF_A0   0
#define OFF_A1   69632
#define OFF_WHI  139264
#define OFF_WLO  174080
#define OFF_PRM  208896
#define SMEM_MMA (OFF_PRM + 3 * 512)   // 210,432 B

// ---------------- ptx helpers (sm_80-level only; no tcgen05!) ----------------
__device__ __forceinline__ void ldsm_x4(uint32_t* r, uint32_t addr) {
    asm volatile("ldmatrix.sync.aligned.m8n8.x4.shared.b16 {%0,%1,%2,%3}, [%4];"
                 : "=r"(r[0]), "=r"(r[1]), "=r"(r[2]), "=r"(r[3]) : "r"(addr));
}
__device__ __forceinline__ void ldsm_x4_t(uint32_t* r, uint32_t addr) {
    asm volatile("ldmatrix.sync.aligned.m8n8.x4.trans.shared.b16 {%0,%1,%2,%3}, [%4];"
                 : "=r"(r[0]), "=r"(r[1]), "=r"(r[2]), "=r"(r[3]) : "r"(addr));
}
__device__ __forceinline__ void mma_bf16(float* c, const uint32_t* a, const uint32_t* b) {
    asm volatile("mma.sync.aligned.m16n8k16.row.col.f32.bf16.bf16.f32 "
                 "{%0,%1,%2,%3}, {%4,%5,%6,%7}, {%8,%9}, {%0,%1,%2,%3};"
                 : "+f"(c[0]), "+f"(c[1]), "+f"(c[2]), "+f"(c[3])
                 : "r"(a[0]), "r"(a[1]), "r"(a[2]), "r"(a[3]), "r"(b[0]), "r"(b[1]));
}

// fast split: hi = truncated top-16 bits (PRMT pack), lo = rn-bf16 of residual
__device__ __forceinline__ void split4(float4 v, uint2& hi, uint2& lo) {
    uint32_t u0 = __float_as_uint(v.x), u1 = __float_as_uint(v.y),
             u2 = __float_as_uint(v.z), u3 = __float_as_uint(v.w);
    asm("prmt.b32 %0, %1, %2, 0x7632;" : "=r"(hi.x) : "r"(u0), "r"(u1));
    asm("prmt.b32 %0, %1, %2, 0x7632;" : "=r"(hi.y) : "r"(u2), "r"(u3));
    float l0 = v.x - __uint_as_float(u0 & 0xFFFF0000u);
    float l1 = v.y - __uint_as_float(u1 & 0xFFFF0000u);
    float l2 = v.z - __uint_as_float(u2 & 0xFFFF0000u);
    float l3 = v.w - __uint_as_float(u3 & 0xFFFF0000u);
    asm("cvt.rn.bf16x2.f32 %0, %1, %2;" : "=r"(lo.x) : "f"(l1), "f"(l0));
    asm("cvt.rn.bf16x2.f32 %0, %1, %2;" : "=r"(lo.y) : "f"(l3), "f"(l2));
}

// transform + split + STS of one float4 at absolute float4-col qq
template <int MODE>
__device__ __forceinline__ void conv_store(float4 v, bool valid, int qq,
                                           const float4* __restrict__ trow,
                                           const float* __restrict__ psm,
                                           unsigned char* Ah, int row_l) {
    if (valid) {
        if (MODE == 1) {
            float4 t = __ldg(trow + qq);
            v.x += t.x; v.y += t.y; v.z += t.z; v.w += t.w;
        } else if (MODE == 2) {
            int k0 = qq * 4;
            v.x = fmaxf(fmaf(v.x, psm[128 + k0 + 0], psm[256 + k0 + 0]), 0.f);
            v.y = fmaxf(fmaf(v.y, psm[128 + k0 + 1], psm[256 + k0 + 1]), 0.f);
            v.z = fmaxf(fmaf(v.z, psm[128 + k0 + 2], psm[256 + k0 + 2]), 0.f);
            v.w = fmaxf(fmaf(v.w, psm[128 + k0 + 3], psm[256 + k0 + 3]), 0.f);
        }
    } else {
        v = make_float4(0.f, 0.f, 0.f, 0.f);
    }
    uint2 hi, lo;
    split4(v, hi, lo);
    uint32_t off = (uint32_t)row_l * 272 + (uint32_t)qq * 8;
    *(uint2*)(Ah + off) = hi;
    *(uint2*)(Ah + 34816 + off) = lo;
}

// ---------------- misc small kernels ----------------
__global__ void zero_kernel() {
    const int n1 = NGRAPHS * NF;
    const int ntot = n1 + 4 * NF;
    for (int i = blockIdx.x * blockDim.x + threadIdx.x; i < ntot;
         i += gridDim.x * blockDim.x) {
        if (i < n1)               g_S[i] = 0.f;
        else if (i < n1 + 2 * NF) g_stat0[i - n1] = 0.f;
        else                      g_stat1[i - n1 - 2 * NF] = 0.f;
    }
}

// float4 lanes: 32 threads/row, 4 row-lanes, run-length accumulate per lane
__global__ void seg_sum_kernel(const float* __restrict__ x,
                               const int* __restrict__ batch, int M) {
    const int rg = threadIdx.x >> 5;   // row lane 0..3
    const int c4 = threadIdx.x & 31;   // float4 column
    int r0 = blockIdx.x * 256;
    int rend = min(r0 + 256, M);
    float4 acc = make_float4(0.f, 0.f, 0.f, 0.f);
    int cur = -1;
    for (int r = r0 + rg; r < rend; r += 4) {
        int b = __ldg(&batch[r]);
        if (b != cur) {
            if (cur >= 0) {
                float* d = &g_S[(size_t)cur * NF + c4 * 4];
                atomicAdd(d + 0, acc.x); atomicAdd(d + 1, acc.y);
                atomicAdd(d + 2, acc.z); atomicAdd(d + 3, acc.w);
            }
            acc = make_float4(0.f, 0.f, 0.f, 0.f); cur = b;
        }
        float4 v = __ldg((const float4*)x + (size_t)r * 32 + c4);
        acc.x += v.x; acc.y += v.y; acc.z += v.z; acc.w += v.w;
    }
    if (cur >= 0) {
        float* d = &g_S[(size_t)cur * NF + c4 * 4];
        atomicAdd(d + 0, acc.x); atomicAdd(d + 1, acc.y);
        atomicAdd(d + 2, acc.z); atomicAdd(d + 3, acc.w);
    }
}

__global__ void bn_prep_kernel(const float* __restrict__ sum, const float* __restrict__ ss,
                               float n, const float* __restrict__ g,
                               const float* __restrict__ b,
                               float* __restrict__ sc, float* __restrict__ sh) {
    const int c = threadIdx.x;
    float mu = sum[c] / n;
    float var = ss[c] / n - mu * mu;
    float rstd = rsqrtf(var + EPSBN);
    float s = rstd * g[c];
    sc[c] = s;
    sh[c] = b[c] - mu * s;
}

__global__ void make_T_kernel() {
    int i = blockIdx.x * blockDim.x + threadIdx.x;
    if (i < NGRAPHS * NF) {
        int c = i & (NF - 1);
        g_T[i] = fmaxf(fmaf(g_P[i], g_sc0[c], g_sh0[c]), 0.f);
    }
}

// split W_lin, W1, W2 into bf16 hi/lo tiles, layout [k][n] pitch 136 bf16
__global__ void wprep_kernel(const float* __restrict__ WL,
                             const float* __restrict__ W1,
                             const float* __restrict__ W2) {
    int i = blockIdx.x * 256 + threadIdx.x;
    if (i >= NF * NF) return;
    int k = i >> 7, n = i & 127;
    uint32_t off = (uint32_t)k * 272 + (uint32_t)n * 2;
    {
        float v = WL[i];
        __nv_bfloat16 h = __float2bfloat16(v);
        __nv_bfloat16 l = __float2bfloat16(v - __bfloat162float(h));
        *(unsigned short*)((unsigned char*)g_wlhi + off) = __bfloat16_as_ushort(h);
        *(unsigned short*)((unsigned char*)g_wllo + off) = __bfloat16_as_ushort(l);
    }
    {
        float v = W1[i];
        __nv_bfloat16 h = __float2bfloat16(v);
        __nv_bfloat16 l = __float2bfloat16(v - __bfloat162float(h));
        *(unsigned short*)((unsigned char*)g_w1hi + off) = __bfloat16_as_ushort(h);
        *(unsigned short*)((unsigned char*)g_w1lo + off) = __bfloat16_as_ushort(l);
    }
    {
        float v = W2[i];
        __nv_bfloat16 h = __float2bfloat16(v);
        __nv_bfloat16 l = __float2bfloat16(v - __bfloat162float(h));
        *(unsigned short*)((unsigned char*)g_w2hi + off) = __bfloat16_as_ushort(h);
        *(unsigned short*)((unsigned char*)g_w2lo + off) = __bfloat16_as_ushort(l);
    }
}

// ---------------- persistent HMMA GEMM, convert/MMA interleaved ----------------
// 256 threads / 8 warps (2x4 warp grid, 64x32 microtile per warp).
// Double-buffered A(hi/lo): convert(tile+1) interleaves with mma(tile).
// MODE 0: C = Asrc @ W                       (+ fused BN0 column stats)
// MODE 1: C = (x + T[batch]) @ W + bias      (+ fused BN1 column stats)
// MODE 2: C = relu(Asrc*sc + sh) @ W + bias
template <int MODE>
__global__ void __launch_bounds__(256, 1)
gemm_mma(const float* __restrict__ Asrc,
         const uint4* __restrict__ Whi_g, const uint4* __restrict__ Wlo_g,
         const float* __restrict__ bias,
         const float* __restrict__ Tm, const int* __restrict__ batch,
         const float* __restrict__ sc, const float* __restrict__ sh,
         float* __restrict__ C, float* __restrict__ stats, int M, int ntiles) {
    constexpr bool STATS = (MODE != 2);
    constexpr bool HASBIAS = (MODE != 0);

    extern __shared__ unsigned char sm[];
    float* psm = (float*)(sm + OFF_PRM);     // bias[128], sc[128], sh[128]
    const uint32_t sb = (uint32_t)__cvta_generic_to_shared(sm);

    const int tid = threadIdx.x;
    const int wid = tid >> 5, lane = tid & 31;
    const int tig = lane & 3, grp = lane >> 2;
    const int warp_m = wid >> 2, warp_n = wid & 3;   // 2x4 grid, 64x32 per warp

    if (tid < NF) {
        psm[tid] = HASBIAS ? __ldg(&bias[tid]) : 0.f;
        if (MODE == 2) { psm[128 + tid] = __ldg(&sc[tid]); psm[256 + tid] = __ldg(&sh[tid]); }
    }
    {
        uint4* dh = (uint4*)(sm + OFF_WHI);
        uint4* dl = (uint4*)(sm + OFF_WLO);
        for (int i = tid; i < 2176; i += 256) {
            dh[i] = __ldg(&Whi_g[i]);
            dl[i] = __ldg(&Wlo_g[i]);
        }
    }

    float bias_r[4][2];
#pragma unroll
    for (int nt = 0; nt < 4; ++nt) {
        bias_r[nt][0] = HASBIAS ? __ldg(&bias[warp_n * 32 + nt * 8 + tig * 2]) : 0.f;
        bias_r[nt][1] = HASBIAS ? __ldg(&bias[warp_n * 32 + nt * 8 + tig * 2 + 1]) : 0.f;
    }

    float cs[4][2], cq[4][2];
    if (STATS) {
#pragma unroll
        for (int nt = 0; nt < 4; ++nt) { cs[nt][0] = cs[nt][1] = 0.f; cq[nt][0] = cq[nt][1] = 0.f; }
    }

    const int row_l = tid >> 1;   // convert role: row within tile (0..127)
    const int half  = tid & 1;    // 64-col half -> float4 cols [half*16, half*16+16)
    const int t0 = blockIdx.x;

    // ---- prologue: convert tile t0 into buffer 0 (serial, once per block) ----
    if (t0 < ntiles) {
        int rg = t0 * 128 + row_l;
        bool valid = rg < M;
        const float4* arow = (const float4*)(Asrc + (size_t)min(rg, M - 1) * NF);
        const float4* trow = nullptr;
        if (MODE == 1)
            trow = (const float4*)(Tm + (size_t)__ldg(&batch[min(rg, M - 1)]) * NF);
        unsigned char* Ah = sm + OFF_A0;
#pragma unroll
        for (int q = 0; q < 16; ++q) {
            int qq = half * 16 + q;
            float4 v = valid ? __ldg(arow + qq) : make_float4(0.f, 0.f, 0.f, 0.f);
            conv_store<MODE>(v, valid, qq, trow, psm, Ah, row_l);
        }
    }
    __syncthreads();

    int parity = 0;
    const int lrow = lane & 15, lsel = lane >> 4;

    for (int tile = t0; tile < ntiles; tile += gridDim.x) {
        const int nxt = tile + gridDim.x;
        const bool hasnext = nxt < ntiles;

        // setup for convert(nxt) into buffer parity^1
        bool validN = false;
        const float4* arowN = nullptr;
        const float4* trowN = nullptr;
        unsigned char* AhN = sm + (parity ? OFF_A0 : OFF_A1);
        float4 c0[2], c1[2];
        if (hasnext) {
            int rgN = nxt * 128 + row_l;
            validN = rgN < M;
            arowN = (const float4*)(Asrc + (size_t)min(rgN, M - 1) * NF);
            if (MODE == 1)
                trowN = (const float4*)(Tm + (size_t)__ldg(&batch[min(rgN, M - 1)]) * NF);
            // depth-2 register pipeline on x loads
            if (validN) {
                c0[0] = __ldg(arowN + half * 16 + 0);
                c1[0] = __ldg(arowN + half * 16 + 1);
                c0[1] = __ldg(arowN + half * 16 + 2);
                c1[1] = __ldg(arowN + half * 16 + 3);
            }
        }

        float acc[4][4][4];
#pragma unroll
        for (int mt = 0; mt < 4; ++mt)
#pragma unroll
            for (int nt = 0; nt < 4; ++nt)
#pragma unroll
                for (int e = 0; e < 4; ++e) acc[mt][nt][e] = 0.f;

        const uint32_t baseA = sb + (parity ? OFF_A1 : OFF_A0);

#pragma unroll
        for (int kt = 0; kt < 8; ++kt) {
            // convert chunk kt for next tile (2 float4), loaded 2 steps ago
            if (hasnext) {
                int slot = kt & 1;
                int qq0 = half * 16 + kt * 2;
                conv_store<MODE>(c0[slot], validN, qq0,     trowN, psm, AhN, row_l);
                conv_store<MODE>(c1[slot], validN, qq0 + 1, trowN, psm, AhN, row_l);
                if (kt < 6 && validN) {
                    c0[slot] = __ldg(arowN + half * 16 + (kt + 2) * 2);
                    c1[slot] = __ldg(arowN + half * 16 + (kt + 2) * 2 + 1);
                }
            }

            const int k0 = kt * 16;
            uint32_t ahi[4][4], alo[4][4], whi[2][4], wlo[2][4];
#pragma unroll
            for (int mt = 0; mt < 4; ++mt) {
                int r = warp_m * 64 + mt * 16 + lrow;
                uint32_t a = baseA + (uint32_t)r * 272 + (uint32_t)(k0 + lsel * 8) * 2;
                ldsm_x4(ahi[mt], a);
                ldsm_x4(alo[mt], a + 34816);
            }
#pragma unroll
            for (int nb = 0; nb < 2; ++nb) {
                int n0 = warp_n * 32 + nb * 16;
                uint32_t a = sb + OFF_WHI + (uint32_t)(k0 + lrow) * 272 + (uint32_t)(n0 + lsel * 8) * 2;
                ldsm_x4_t(whi[nb], a);
                ldsm_x4_t(wlo[nb], a + (OFF_WLO - OFF_WHI));
            }
#pragma unroll
            for (int mt = 0; mt < 4; ++mt)
#pragma unroll
                for (int nt = 0; nt < 4; ++nt) {
                    const uint32_t* bh = &whi[nt >> 1][(nt & 1) * 2];
                    const uint32_t* bl = &wlo[nt >> 1][(nt & 1) * 2];
                    mma_bf16(acc[mt][nt], ahi[mt], bh);
                    mma_bf16(acc[mt][nt], ahi[mt], bl);
                    mma_bf16(acc[mt][nt], alo[mt], bh);
                }
        }

        __syncthreads();   // next-A converted everywhere; all reads of cur-A done

        // ---- epilogue: bias, store, fused stats (registers + STG only) ----
#pragma unroll
        for (int mt = 0; mt < 4; ++mt) {
            int r0 = tile * 128 + warp_m * 64 + mt * 16 + grp;
            int r1 = r0 + 8;
            bool v0 = r0 < M, v1 = r1 < M;
            float* p0 = C + (size_t)r0 * NF + warp_n * 32 + tig * 2;
            float* p1 = C + (size_t)r1 * NF + warp_n * 32 + tig * 2;
#pragma unroll
            for (int nt = 0; nt < 4; ++nt) {
                float d0 = acc[mt][nt][0] + bias_r[nt][0];
                float d1 = acc[mt][nt][1] + bias_r[nt][1];
                float d2 = acc[mt][nt][2] + bias_r[nt][0];
                float d3 = acc[mt][nt][3] + bias_r[nt][1];
                if (v0) {
                    *(float2*)(p0 + nt * 8) = make_float2(d0, d1);
                    if (STATS) { cs[nt][0] += d0; cs[nt][1] += d1; cq[nt][0] += d0 * d0; cq[nt][1] += d1 * d1; }
                }
                if (v1) {
                    *(float2*)(p1 + nt * 8) = make_float2(d2, d3);
                    if (STATS) { cs[nt][0] += d2; cs[nt][1] += d3; cq[nt][0] += d2 * d2; cq[nt][1] += d3 * d3; }
                }
            }
        }
        parity ^= 1;
    }

    // ---- stats flush ----
    if (STATS) {
        __syncthreads();    // A buffers free for reuse as scratch
        float* cs_sm = (float*)sm;          // [8][32]
        float* cq_sm = cs_sm + 256;
#pragma unroll
        for (int nt = 0; nt < 4; ++nt)
#pragma unroll
            for (int par = 0; par < 2; ++par) {
                float s = cs[nt][par], q = cq[nt][par];
#pragma unroll
                for (int msk = 16; msk >= 4; msk >>= 1) {
                    s += __shfl_xor_sync(0xFFFFFFFFu, s, msk);
                    q += __shfl_xor_sync(0xFFFFFFFFu, q, msk);
                }
                if (lane < 4) {
                    cs_sm[wid * 32 + nt * 8 + tig * 2 + par] = s;
                    cq_sm[wid * 32 + nt * 8 + tig * 2 + par] = q;
                }
            }
        __syncthreads();
        if (tid < 128) {
            int col = tid;
            int wn = col >> 5, cl = col & 31;
            atomicAdd(&stats[col], cs_sm[wn * 32 + cl] + cs_sm[(wn + 4) * 32 + cl]);
        } else {
            int col = tid - 128;
            int wn = col >> 5, cl = col & 31;
            atomicAdd(&stats[NF + col], cq_sm[wn * 32 + cl] + cq_sm[(wn + 4) * 32 + cl]);
        }
    }
}

// ---------------- launcher ----------------
extern "C" void kernel_launch(void* const* d_in, const int* in_sizes, int n_in,
                              void* d_out, int out_size) {
    const float* x     = (const float*)d_in[0];
    const int*   batch = (const int*)d_in[3];
    const float* W_lin = (const float*)d_in[4];
    const float* bn_g  = (const float*)d_in[5];
    const float* bn_b  = (const float*)d_in[6];
    const float* W1    = (const float*)d_in[7];
    const float* b1    = (const float*)d_in[8];
    const float* bn1_g = (const float*)d_in[9];
    const float* bn1_b = (const float*)d_in[10];
    const float* W2    = (const float*)d_in[11];
    const float* b2    = (const float*)d_in[12];
    float*       out   = (float*)d_out;

    const int M = in_sizes[0] / NF;   // 500000
    const int ntiles_big = (M + 127) / 128;
    const int ntiles_sml = (NGRAPHS + 127) / 128;   // 79

    float *pS, *pP, *pT, *pH1, *pstat0, *psc0, *psh0, *pstat1, *psc1, *psh1;
    cudaGetSymbolAddress((void**)&pS, g_S);
    cudaGetSymbolAddress((void**)&pP, g_P);
    cudaGetSymbolAddress((void**)&pT, g_T);
    cudaGetSymbolAddress((void**)&pH1, g_H1);
    cudaGetSymbolAddress((void**)&pstat0, g_stat0);
    cudaGetSymbolAddress((void**)&psc0, g_sc0);
    cudaGetSymbolAddress((void**)&psh0, g_sh0);
    cudaGetSymbolAddress((void**)&pstat1, g_stat1);
    cudaGetSymbolAddress((void**)&psc1, g_sc1);
    cudaGetSymbolAddress((void**)&psh1, g_sh1);
    uint4 *pwlh, *pwll, *pw1h, *pw1l, *pw2h, *pw2l;
    cudaGetSymbolAddress((void**)&pwlh, g_wlhi);
    cudaGetSymbolAddress((void**)&pwll, g_wllo);
    cudaGetSymbolAddress((void**)&pw1h, g_w1hi);
    cudaGetSymbolAddress((void**)&pw1l, g_w1lo);
    cudaGetSymbolAddress((void**)&pw2h, g_w2hi);
    cudaGetSymbolAddress((void**)&pw2l, g_w2lo);

    int dev = 0, nsm = 148;
    cudaGetDevice(&dev);
    cudaDeviceGetAttribute(&nsm, cudaDevAttrMultiProcessorCount, dev);
    const int grid_sml = (nsm < ntiles_sml) ? nsm : ntiles_sml;

    cudaFuncSetAttribute(gemm_mma<0>, cudaFuncAttributeMaxDynamicSharedMemorySize, SMEM_MMA);
    cudaFuncSetAttribute(gemm_mma<1>, cudaFuncAttributeMaxDynamicSharedMemorySize, SMEM_MMA);
    cudaFuncSetAttribute(gemm_mma<2>, cudaFuncAttributeMaxDynamicSharedMemorySize, SMEM_MMA);

    // 1) zero accumulators; split+layout weights
    zero_kernel<<<2500, 256>>>();
    wprep_kernel<<<(NF * NF + 255) / 256, 256>>>(W_lin, W1, W2);
    // 2) segment sum
    seg_sum_kernel<<<(M + 255) / 256, 128>>>(x, batch, M);
    // 3) P = S @ W_lin  (HMMA, fused BN0 stats)
    gemm_mma<0><<<grid_sml, 256, SMEM_MMA>>>(pS, pwlh, pwll, nullptr, nullptr, nullptr,
                                             nullptr, nullptr, pP, pstat0, NGRAPHS, ntiles_sml);
    // 4) BN0 scale/shift, T = relu(BN(P))
    bn_prep_kernel<<<1, NF>>>(pstat0, pstat0 + NF, (float)NGRAPHS, bn_g, bn_b, psc0, psh0);
    make_T_kernel<<<(NGRAPHS * NF + 255) / 256, 256>>>();
    // 5) H1 = (x + T[batch]) @ W1 + b1  (HMMA, fused BN1 stats)
    gemm_mma<1><<<nsm, 256, SMEM_MMA>>>(x, pw1h, pw1l, b1, pT, batch,
                                        nullptr, nullptr, pH1, pstat1, M, ntiles_big);
    // 6) BN1 scale/shift
    bn_prep_kernel<<<1, NF>>>(pstat1, pstat1 + NF, (float)M, bn1_g, bn1_b, psc1, psh1);
    // 7) out = relu(BN(H1)) @ W2 + b2  (HMMA)
    gemm_mma<2><<<nsm, 256, SMEM_MMA>>>(pH1, pw2h, pw2l, b2, nullptr, nullptr,
                                        psc1, psh1, out, nullptr, M, ntiles_big);
}

// round 8
// speedup vs baseline: 1.0848x; 1.0756x over previous
#include <cuda_runtime.h>
#include <cuda_bf16.h>
#include <cstdint>

// ---------------- problem constants ----------------
#define NF 128
#define NGRAPHS 10000
#define MAXM 500000
#define EPSBN 1e-5f

// ---------------- scratch globals (no allocs allowed) ----------------
__device__ float g_S[NGRAPHS * NF];
__device__ float g_P[NGRAPHS * NF];
__device__ float g_H1[(size_t)MAXM * NF];
__device__ float g_stat0[2 * NF];            // BN0 sum/sumsq (atomics)
__device__ float g_sc0[NF], g_sh0[NF];
__device__ float g_stat1[2 * NF];            // BN1 sum/sumsq (atomics)
__device__ float g_sc1[NF], g_sh1[NF];
__device__ unsigned g_sync0, g_sync1;        // last-block counters
// weight tiles, bf16 hi/lo, layout [k][n] with pitch 136 bf16 (272B/row), 34816B
__device__ uint4 g_wlhi[2176], g_wllo[2176];
__device__ uint4 g_w1hi[2176], g_w1lo[2176], g_w2hi[2176], g_w2lo[2176];

// ---------------- smem layout (dynamic) ----------------
#define OFF_STAGE 0
#define OFF_AHI   65536
#define OFF_ALO   (65536 + 34816)
#define OFF_WHI   (65536 + 2 * 34816)
#define OFF_WLO   (65536 + 3 * 34816)
#define OFF_PRM   (65536 + 4 * 34816)
#define SMEM_MMA  (OFF_PRM + 3 * 512)   // 206,336 B

// ---------------- ptx helpers (sm_80-level only; no tcgen05!) ----------------
__device__ __forceinline__ void ldsm_x4(uint32_t* r, uint32_t addr) {
    asm volatile("ldmatrix.sync.aligned.m8n8.x4.shared.b16 {%0,%1,%2,%3}, [%4];"
                 : "=r"(r[0]), "=r"(r[1]), "=r"(r[2]), "=r"(r[3]) : "r"(addr));
}
__device__ __forceinline__ void ldsm_x4_t(uint32_t* r, uint32_t addr) {
    asm volatile("ldmatrix.sync.aligned.m8n8.x4.trans.shared.b16 {%0,%1,%2,%3}, [%4];"
                 : "=r"(r[0]), "=r"(r[1]), "=r"(r[2]), "=r"(r[3]) : "r"(addr));
}
__device__ __forceinline__ void mma_bf16(float* c, const uint32_t* a, const uint32_t* b) {
    asm volatile("mma.sync.aligned.m16n8k16.row.col.f32.bf16.bf16.f32 "
                 "{%0,%1,%2,%3}, {%4,%5,%6,%7}, {%8,%9}, {%0,%1,%2,%3};"
                 : "+f"(c[0]), "+f"(c[1]), "+f"(c[2]), "+f"(c[3])
                 : "r"(a[0]), "r"(a[1]), "r"(a[2]), "r"(a[3]), "r"(b[0]), "r"(b[1]));
}
__device__ __forceinline__ void cp16(uint32_t dst, const void* src, int sz) {
    asm volatile("cp.async.cg.shared.global [%0], [%1], 16, %2;"
                 :: "r"(dst), "l"(src), "r"(sz));
}
#define CP_COMMIT() asm volatile("cp.async.commit_group;")
#define CP_WAIT0()  asm volatile("cp.async.wait_group 0;")

// fast split: hi = truncated top-16 bits (PRMT pack), lo = rn-bf16 of residual
__device__ __forceinline__ void split4(float4 v, uint2& hi, uint2& lo) {
    uint32_t u0 = __float_as_uint(v.x), u1 = __float_as_uint(v.y),
             u2 = __float_as_uint(v.z), u3 = __float_as_uint(v.w);
    asm("prmt.b32 %0, %1, %2, 0x7632;" : "=r"(hi.x) : "r"(u0), "r"(u1));
    asm("prmt.b32 %0, %1, %2, 0x7632;" : "=r"(hi.y) : "r"(u2), "r"(u3));
    float l0 = v.x - __uint_as_float(u0 & 0xFFFF0000u);
    float l1 = v.y - __uint_as_float(u1 & 0xFFFF0000u);
    float l2 = v.z - __uint_as_float(u2 & 0xFFFF0000u);
    float l3 = v.w - __uint_as_float(u3 & 0xFFFF0000u);
    asm("cvt.rn.bf16x2.f32 %0, %1, %2;" : "=r"(lo.x) : "f"(l1), "f"(l0));
    asm("cvt.rn.bf16x2.f32 %0, %1, %2;" : "=r"(lo.y) : "f"(l3), "f"(l2));
}

// ---------------- init: zero accumulators + split/layout weights ----------------
__global__ void init_kernel(const float* __restrict__ WL,
                            const float* __restrict__ W1,
                            const float* __restrict__ W2) {
    const int gtid = blockIdx.x * 256 + threadIdx.x;
    // zero S + stats + counters
    const int n1 = NGRAPHS * NF;
    for (int i = gtid; i < n1; i += gridDim.x * 256) g_S[i] = 0.f;
    if (gtid < 2 * NF) { g_stat0[gtid] = 0.f; g_stat1[gtid] = 0.f; }
    if (gtid == 0) { g_sync0 = 0u; g_sync1 = 0u; }
    // weight prep: first 64 blocks cover 128x128
    if (gtid < NF * NF) {
        int k = gtid >> 7, n = gtid & 127;
        uint32_t off = (uint32_t)k * 272 + (uint32_t)n * 2;
        float v; __nv_bfloat16 h, l;
        v = WL[gtid]; h = __float2bfloat16(v); l = __float2bfloat16(v - __bfloat162float(h));
        *(unsigned short*)((unsigned char*)g_wlhi + off) = __bfloat16_as_ushort(h);
        *(unsigned short*)((unsigned char*)g_wllo + off) = __bfloat16_as_ushort(l);
        v = W1[gtid]; h = __float2bfloat16(v); l = __float2bfloat16(v - __bfloat162float(h));
        *(unsigned short*)((unsigned char*)g_w1hi + off) = __bfloat16_as_ushort(h);
        *(unsigned short*)((unsigned char*)g_w1lo + off) = __bfloat16_as_ushort(l);
        v = W2[gtid]; h = __float2bfloat16(v); l = __float2bfloat16(v - __bfloat162float(h));
        *(unsigned short*)((unsigned char*)g_w2hi + off) = __bfloat16_as_ushort(h);
        *(unsigned short*)((unsigned char*)g_w2lo + off) = __bfloat16_as_ushort(l);
    }
}

// float4 lanes: 32 threads/row, 4 row-lanes, run-length accumulate per lane
__global__ void seg_sum_kernel(const float* __restrict__ x,
                               const int* __restrict__ batch, int M) {
    const int rg = threadIdx.x >> 5;   // row lane 0..3
    const int c4 = threadIdx.x & 31;   // float4 column
    int r0 = blockIdx.x * 256;
    int rend = min(r0 + 256, M);
    float4 acc = make_float4(0.f, 0.f, 0.f, 0.f);
    int cur = -1;
    for (int r = r0 + rg; r < rend; r += 4) {
        int b = __ldg(&batch[r]);
        if (b != cur) {
            if (cur >= 0) {
                float* d = &g_S[(size_t)cur * NF + c4 * 4];
                atomicAdd(d + 0, acc.x); atomicAdd(d + 1, acc.y);
                atomicAdd(d + 2, acc.z); atomicAdd(d + 3, acc.w);
            }
            acc = make_float4(0.f, 0.f, 0.f, 0.f); cur = b;
        }
        float4 v = __ldg((const float4*)x + (size_t)r * 32 + c4);
        acc.x += v.x; acc.y += v.y; acc.z += v.z; acc.w += v.w;
    }
    if (cur >= 0) {
        float* d = &g_S[(size_t)cur * NF + c4 * 4];
        atomicAdd(d + 0, acc.x); atomicAdd(d + 1, acc.y);
        atomicAdd(d + 2, acc.z); atomicAdd(d + 3, acc.w);
    }
}

// ---------------- persistent HMMA (mma.sync bf16 split) GEMM ----------------
// 256 threads / 8 warps (2x4 warp grid, 64x32 microtile per warp).
// MODE 0: C = Asrc @ W                                  (+ BN0 stats + bn-prep tail)
// MODE 1: C = (x + relu(P[batch]*sc+sh)) @ W + bias     (+ BN1 stats + bn-prep tail)
// MODE 2: C = relu(Asrc*sc + sh) @ W + bias
template <int MODE>
__global__ void __launch_bounds__(256, 1)
gemm_mma(const float* __restrict__ Asrc,
         const uint4* __restrict__ Whi_g, const uint4* __restrict__ Wlo_g,
         const float* __restrict__ bias,
         const float* __restrict__ Tm, const int* __restrict__ batch,
         const float* __restrict__ sc, const float* __restrict__ sh,
         float* __restrict__ C, float* __restrict__ stats,
         const float* __restrict__ gamma, const float* __restrict__ beta,
         float nrows, float* __restrict__ sc_out, float* __restrict__ sh_out,
         unsigned* __restrict__ sync_ctr, int M, int ntiles) {
    constexpr bool STATS = (MODE != 2);
    constexpr bool HASBIAS = (MODE != 0);

    extern __shared__ unsigned char sm[];
    float4* stage = (float4*)(sm + OFF_STAGE);
    float*  psm   = (float*)(sm + OFF_PRM);     // bias[128], sc[128], sh[128]
    const uint32_t sb = (uint32_t)__cvta_generic_to_shared(sm);

    const int tid = threadIdx.x;
    const int wid = tid >> 5, lane = tid & 31;
    const int tig = lane & 3, grp = lane >> 2;
    const int warp_m = wid >> 2, warp_n = wid & 3;

    if (tid < NF) {
        psm[tid] = HASBIAS ? __ldg(&bias[tid]) : 0.f;
        if (MODE != 0) { psm[128 + tid] = __ldg(&sc[tid]); psm[256 + tid] = __ldg(&sh[tid]); }
    }
    {
        uint4* dh = (uint4*)(sm + OFF_WHI);
        uint4* dl = (uint4*)(sm + OFF_WLO);
        for (int i = tid; i < 2176; i += 256) {
            dh[i] = __ldg(&Whi_g[i]);
            dl[i] = __ldg(&Wlo_g[i]);
        }
    }

    float bias_r[4][2];
#pragma unroll
    for (int nt = 0; nt < 4; ++nt) {
        bias_r[nt][0] = HASBIAS ? __ldg(&bias[warp_n * 32 + nt * 8 + tig * 2]) : 0.f;
        bias_r[nt][1] = HASBIAS ? __ldg(&bias[warp_n * 32 + nt * 8 + tig * 2 + 1]) : 0.f;
    }

    float cs[4][2], cq[4][2];
    if (STATS) {
#pragma unroll
        for (int nt = 0; nt < 4; ++nt) { cs[nt][0] = cs[nt][1] = 0.f; cq[nt][0] = cq[nt][1] = 0.f; }
    }

    // prologue loads for first tile
    const int t0 = blockIdx.x;
    {
#pragma unroll
        for (int i = 0; i < 16; ++i) {
            int idx = tid + 256 * i;
            int r = idx >> 5, q = idx & 31;
            int rg = t0 * 128 + r;
            const float4* src = (const float4*)Asrc + (size_t)min(rg, M - 1) * 32 + q;
            uint32_t dst = sb + OFF_STAGE + (uint32_t)(r * 32 + (q ^ (r & 31))) * 16;
            cp16(dst, src, rg < M ? 16 : 0);
        }
    }
    CP_COMMIT();

    const int row_l = tid >> 1;   // convert role: row within tile
    const int half  = tid & 1;    // which 64-col half

    for (int tile = t0; tile < ntiles; tile += gridDim.x) {
        CP_WAIT0();
        __syncthreads();

        // ---- convert stage -> Ahi/Alo (fused transform) ----
        {
            int rg = tile * 128 + row_l;
            const float4* trow = nullptr;
            if (MODE == 1) {
                int g = __ldg(&batch[min(rg, M - 1)]);
                trow = (const float4*)(Tm + (size_t)g * NF);
            }
            unsigned char* Ah = sm + OFF_AHI;
            unsigned char* Al = sm + OFF_ALO;
#pragma unroll
            for (int q = 0; q < 16; ++q) {
                int qq = half * 16 + q;            // float4 col idx 0..31
                float4 v = stage[row_l * 32 + (qq ^ (row_l & 31))];
                if (MODE == 1) {
                    // v += relu(P[g] * sc0 + sh0)   (make_T fused)
                    float4 t = __ldg(trow + qq);
                    int k0 = qq * 4;
                    v.x += fmaxf(fmaf(t.x, psm[128 + k0 + 0], psm[256 + k0 + 0]), 0.f);
                    v.y += fmaxf(fmaf(t.y, psm[128 + k0 + 1], psm[256 + k0 + 1]), 0.f);
                    v.z += fmaxf(fmaf(t.z, psm[128 + k0 + 2], psm[256 + k0 + 2]), 0.f);
                    v.w += fmaxf(fmaf(t.w, psm[128 + k0 + 3], psm[256 + k0 + 3]), 0.f);
                } else if (MODE == 2) {
                    int k0 = qq * 4;
                    v.x = fmaxf(fmaf(v.x, psm[128 + k0 + 0], psm[256 + k0 + 0]), 0.f);
                    v.y = fmaxf(fmaf(v.y, psm[128 + k0 + 1], psm[256 + k0 + 1]), 0.f);
                    v.z = fmaxf(fmaf(v.z, psm[128 + k0 + 2], psm[256 + k0 + 2]), 0.f);
                    v.w = fmaxf(fmaf(v.w, psm[128 + k0 + 3], psm[256 + k0 + 3]), 0.f);
                }
                uint2 hi, lo;
                split4(v, hi, lo);
                uint32_t off = (uint32_t)row_l * 272 + (uint32_t)qq * 8;
                *(uint2*)(Ah + off) = hi;
                *(uint2*)(Al + off) = lo;
            }
        }
        __syncthreads();

        // ---- prefetch next tile into stage ----
        {
            int nt_ = tile + gridDim.x;
            if (nt_ < ntiles) {
#pragma unroll
                for (int i = 0; i < 16; ++i) {
                    int idx = tid + 256 * i;
                    int r = idx >> 5, q = idx & 31;
                    int rg = nt_ * 128 + r;
                    const float4* src = (const float4*)Asrc + (size_t)min(rg, M - 1) * 32 + q;
                    uint32_t dst = sb + OFF_STAGE + (uint32_t)(r * 32 + (q ^ (r & 31))) * 16;
                    cp16(dst, src, rg < M ? 16 : 0);
                }
            }
            CP_COMMIT();
        }

        // ---- HMMA mainloop: 3-chain bf16 split into fp32 acc ----
        float acc[4][4][4];
#pragma unroll
        for (int mt = 0; mt < 4; ++mt)
#pragma unroll
            for (int nt = 0; nt < 4; ++nt)
#pragma unroll
                for (int e = 0; e < 4; ++e) acc[mt][nt][e] = 0.f;

        const int lrow = lane & 15, lsel = lane >> 4;
#pragma unroll
        for (int kt = 0; kt < 8; ++kt) {
            const int k0 = kt * 16;
            uint32_t ahi[4][4], alo[4][4], whi[2][4], wlo[2][4];
#pragma unroll
            for (int mt = 0; mt < 4; ++mt) {
                int r = warp_m * 64 + mt * 16 + lrow;
                uint32_t a = sb + OFF_AHI + (uint32_t)r * 272 + (uint32_t)(k0 + lsel * 8) * 2;
                ldsm_x4(ahi[mt], a);
                ldsm_x4(alo[mt], a + (OFF_ALO - OFF_AHI));
            }
#pragma unroll
            for (int nb = 0; nb < 2; ++nb) {
                int n0 = warp_n * 32 + nb * 16;
                uint32_t a = sb + OFF_WHI + (uint32_t)(k0 + lrow) * 272 + (uint32_t)(n0 + lsel * 8) * 2;
                ldsm_x4_t(whi[nb], a);
                ldsm_x4_t(wlo[nb], a + (OFF_WLO - OFF_WHI));
            }
#pragma unroll
            for (int mt = 0; mt < 4; ++mt)
#pragma unroll
                for (int nt = 0; nt < 4; ++nt) {
                    const uint32_t* bh = &whi[nt >> 1][(nt & 1) * 2];
                    const uint32_t* bl = &wlo[nt >> 1][(nt & 1) * 2];
                    mma_bf16(acc[mt][nt], ahi[mt], bh);
                    mma_bf16(acc[mt][nt], ahi[mt], bl);
                    mma_bf16(acc[mt][nt], alo[mt], bh);
                }
        }

        // ---- epilogue: bias, store, fused stats ----
#pragma unroll
        for (int mt = 0; mt < 4; ++mt) {
            int r0 = tile * 128 + warp_m * 64 + mt * 16 + grp;
            int r1 = r0 + 8;
            bool v0 = r0 < M, v1 = r1 < M;
            float* p0 = C + (size_t)r0 * NF + warp_n * 32 + tig * 2;
            float* p1 = C + (size_t)r1 * NF + warp_n * 32 + tig * 2;
#pragma unroll
            for (int nt = 0; nt < 4; ++nt) {
                float c0 = acc[mt][nt][0] + bias_r[nt][0];
                float c1 = acc[mt][nt][1] + bias_r[nt][1];
                float c2 = acc[mt][nt][2] + bias_r[nt][0];
                float c3 = acc[mt][nt][3] + bias_r[nt][1];
                if (v0) {
                    *(float2*)(p0 + nt * 8) = make_float2(c0, c1);
                    if (STATS) { cs[nt][0] += c0; cs[nt][1] += c1; cq[nt][0] += c0 * c0; cq[nt][1] += c1 * c1; }
                }
                if (v1) {
                    *(float2*)(p1 + nt * 8) = make_float2(c2, c3);
                    if (STATS) { cs[nt][0] += c2; cs[nt][1] += c3; cq[nt][0] += c2 * c2; cq[nt][1] += c3 * c3; }
                }
            }
        }
    }

    // ---- stats flush + last-block bn-prep ----
    if (STATS) {
        CP_WAIT0();         // drain any pending prologue copies into stage
        __syncthreads();    // stage now free for reuse
        float* cs_sm = (float*)(sm + OFF_STAGE);          // [8][32]
        float* cq_sm = cs_sm + 256;
#pragma unroll
        for (int nt = 0; nt < 4; ++nt)
#pragma unroll
            for (int par = 0; par < 2; ++par) {
                float s = cs[nt][par], q = cq[nt][par];
#pragma unroll
                for (int msk = 16; msk >= 4; msk >>= 1) {
                    s += __shfl_xor_sync(0xFFFFFFFFu, s, msk);
                    q += __shfl_xor_sync(0xFFFFFFFFu, q, msk);
                }
                if (lane < 4) {
                    cs_sm[wid * 32 + nt * 8 + tig * 2 + par] = s;
                    cq_sm[wid * 32 + nt * 8 + tig * 2 + par] = q;
                }
            }
        __syncthreads();
        if (tid < 128) {
            int col = tid;
            int wn = col >> 5, cl = col & 31;
            atomicAdd(&stats[col], cs_sm[wn * 32 + cl] + cs_sm[(wn + 4) * 32 + cl]);
        } else {
            int col = tid - 128;
            int wn = col >> 5, cl = col & 31;
            atomicAdd(&stats[NF + col], cq_sm[wn * 32 + cl] + cq_sm[(wn + 4) * 32 + cl]);
        }

        // last block computes BN scale/shift
        __shared__ unsigned last_f;
        __threadfence();
        __syncthreads();
        if (tid == 0) last_f = (atomicAdd(sync_ctr, 1u) == (unsigned)(gridDim.x - 1)) ? 1u : 0u;
        __syncthreads();
        if (last_f) {
            if (tid < NF) {
                float su = atomicAdd(&stats[tid], 0.f);       // L2-coherent read
                float sq = atomicAdd(&stats[NF + tid], 0.f);
                float mu = su / nrows;
                float var = sq / nrows - mu * mu;
                float s = rsqrtf(var + EPSBN) * __ldg(&gamma[tid]);
                sc_out[tid] = s;
                sh_out[tid] = __ldg(&beta[tid]) - mu * s;
            }
        }
    }
}

// ---------------- launcher ----------------
extern "C" void kernel_launch(void* const* d_in, const int* in_sizes, int n_in,
                              void* d_out, int out_size) {
    const float* x     = (const float*)d_in[0];
    const int*   batch = (const int*)d_in[3];
    const float* W_lin = (const float*)d_in[4];
    const float* bn_g  = (const float*)d_in[5];
    const float* bn_b  = (const float*)d_in[6];
    const float* W1    = (const float*)d_in[7];
    const float* b1    = (const float*)d_in[8];
    const float* bn1_g = (const float*)d_in[9];
    const float* bn1_b = (const float*)d_in[10];
    const float* W2    = (const float*)d_in[11];
    const float* b2    = (const float*)d_in[12];
    float*       out   = (float*)d_out;

    const int M = in_sizes[0] / NF;   // 500000
    const int ntiles_big = (M + 127) / 128;
    const int ntiles_sml = (NGRAPHS + 127) / 128;   // 79

    float *pS, *pP, *pH1, *pstat0, *psc0, *psh0, *pstat1, *psc1, *psh1;
    cudaGetSymbolAddress((void**)&pS, g_S);
    cudaGetSymbolAddress((void**)&pP, g_P);
    cudaGetSymbolAddress((void**)&pH1, g_H1);
    cudaGetSymbolAddress((void**)&pstat0, g_stat0);
    cudaGetSymbolAddress((void**)&psc0, g_sc0);
    cudaGetSymbolAddress((void**)&psh0, g_sh0);
    cudaGetSymbolAddress((void**)&pstat1, g_stat1);
    cudaGetSymbolAddress((void**)&psc1, g_sc1);
    cudaGetSymbolAddress((void**)&psh1, g_sh1);
    unsigned *psync0, *psync1;
    cudaGetSymbolAddress((void**)&psync0, g_sync0);
    cudaGetSymbolAddress((void**)&psync1, g_sync1);
    uint4 *pwlh, *pwll, *pw1h, *pw1l, *pw2h, *pw2l;
    cudaGetSymbolAddress((void**)&pwlh, g_wlhi);
    cudaGetSymbolAddress((void**)&pwll, g_wllo);
    cudaGetSymbolAddress((void**)&pw1h, g_w1hi);
    cudaGetSymbolAddress((void**)&pw1l, g_w1lo);
    cudaGetSymbolAddress((void**)&pw2h, g_w2hi);
    cudaGetSymbolAddress((void**)&pw2l, g_w2lo);

    int dev = 0, nsm = 148;
    cudaGetDevice(&dev);
    cudaDeviceGetAttribute(&nsm, cudaDevAttrMultiProcessorCount, dev);
    const int grid_sml = (nsm < ntiles_sml) ? nsm : ntiles_sml;

    cudaFuncSetAttribute(gemm_mma<0>, cudaFuncAttributeMaxDynamicSharedMemorySize, SMEM_MMA);
    cudaFuncSetAttribute(gemm_mma<1>, cudaFuncAttributeMaxDynamicSharedMemorySize, SMEM_MMA);
    cudaFuncSetAttribute(gemm_mma<2>, cudaFuncAttributeMaxDynamicSharedMemorySize, SMEM_MMA);

    // (1) init: zero accumulators + weight split/layout
    init_kernel<<<2500, 256>>>(W_lin, W1, W2);
    // (2) segment sum
    seg_sum_kernel<<<(M + 255) / 256, 128>>>(x, batch, M);
    // (3) P = S @ W_lin  (HMMA, fused BN0 stats + bn-prep tail)
    gemm_mma<0><<<grid_sml, 256, SMEM_MMA>>>(pS, pwlh, pwll, nullptr, nullptr, nullptr,
                                             nullptr, nullptr, pP, pstat0,
                                             bn_g, bn_b, (float)NGRAPHS, psc0, psh0,
                                             psync0, NGRAPHS, ntiles_sml);
    // (4) H1 = (x + relu(BN0(P))[batch]) @ W1 + b1  (HMMA, fused BN1 stats + bn-prep)
    gemm_mma<1><<<nsm, 256, SMEM_MMA>>>(x, pw1h, pw1l, b1, pP, batch,
                                        psc0, psh0, pH1, pstat1,
                                        bn1_g, bn1_b, (float)M, psc1, psh1,
                                        psync1, M, ntiles_big);
    // (5) out = relu(BN1(H1)) @ W2 + b2  (HMMA)
    gemm_mma<2><<<nsm, 256, SMEM_MMA>>>(pH1, pw2h, pw2l, b2, nullptr, nullptr,
                                        psc1, psh1, out, nullptr,
                                        nullptr, nullptr, 0.f, nullptr, nullptr,
                                        nullptr, M, ntiles_big);
}

// round 9
// speedup vs baseline: 1.1172x; 1.0299x over previous
#include <cuda_runtime.h>
#include <cuda_bf16.h>
#include <cstdint>

// ---------------- problem constants ----------------
#define NF 128
#define NGRAPHS 10000
#define MAXM 500000
#define EPSBN 1e-5f
#define BM 64                       // rows per tile

// ---------------- scratch globals (no allocs allowed) ----------------
__device__ float g_S[NGRAPHS * NF];
__device__ float g_P[NGRAPHS * NF];
__device__ float g_H1[(size_t)MAXM * NF];
__device__ float g_stat0[2 * NF];            // BN0 sum/sumsq (atomics)
__device__ float g_sc0[NF], g_sh0[NF];
__device__ float g_stat1[2 * NF];            // BN1 sum/sumsq (atomics)
__device__ float g_sc1[NF], g_sh1[NF];
__device__ unsigned g_sync0, g_sync1;        // last-block counters
// weight tiles, bf16 hi/lo, layout [k][n] with pitch 136 bf16 (272B/row), 34816B
__device__ uint4 g_wlhi[2176], g_wllo[2176];
__device__ uint4 g_w1hi[2176], g_w1lo[2176], g_w2hi[2176], g_w2lo[2176];

// ---------------- smem layout (dynamic) ----------------
// A(hi/lo) 2*17408, W(hi/lo) 2*34816, params 1536  -> 105,984 B (2 CTAs/SM)
#define OFF_AHI  0
#define OFF_ALO  17408
#define OFF_WHI  34816
#define OFF_WLO  69632
#define OFF_PRM  104448
#define SMEM_MMA (OFF_PRM + 3 * 512)

// ---------------- ptx helpers (sm_80-level only; no tcgen05!) ----------------
__device__ __forceinline__ void ldsm_x4(uint32_t* r, uint32_t addr) {
    asm volatile("ldmatrix.sync.aligned.m8n8.x4.shared.b16 {%0,%1,%2,%3}, [%4];"
                 : "=r"(r[0]), "=r"(r[1]), "=r"(r[2]), "=r"(r[3]) : "r"(addr));
}
__device__ __forceinline__ void ldsm_x4_t(uint32_t* r, uint32_t addr) {
    asm volatile("ldmatrix.sync.aligned.m8n8.x4.trans.shared.b16 {%0,%1,%2,%3}, [%4];"
                 : "=r"(r[0]), "=r"(r[1]), "=r"(r[2]), "=r"(r[3]) : "r"(addr));
}
__device__ __forceinline__ void mma_bf16(float* c, const uint32_t* a, const uint32_t* b) {
    asm volatile("mma.sync.aligned.m16n8k16.row.col.f32.bf16.bf16.f32 "
                 "{%0,%1,%2,%3}, {%4,%5,%6,%7}, {%8,%9}, {%0,%1,%2,%3};"
                 : "+f"(c[0]), "+f"(c[1]), "+f"(c[2]), "+f"(c[3])
                 : "r"(a[0]), "r"(a[1]), "r"(a[2]), "r"(a[3]), "r"(b[0]), "r"(b[1]));
}

// fast split: hi = truncated top-16 bits (PRMT pack), lo = rn-bf16 of residual
__device__ __forceinline__ void split4(float4 v, uint2& hi, uint2& lo) {
    uint32_t u0 = __float_as_uint(v.x), u1 = __float_as_uint(v.y),
             u2 = __float_as_uint(v.z), u3 = __float_as_uint(v.w);
    asm("prmt.b32 %0, %1, %2, 0x7632;" : "=r"(hi.x) : "r"(u0), "r"(u1));
    asm("prmt.b32 %0, %1, %2, 0x7632;" : "=r"(hi.y) : "r"(u2), "r"(u3));
    float l0 = v.x - __uint_as_float(u0 & 0xFFFF0000u);
    float l1 = v.y - __uint_as_float(u1 & 0xFFFF0000u);
    float l2 = v.z - __uint_as_float(u2 & 0xFFFF0000u);
    float l3 = v.w - __uint_as_float(u3 & 0xFFFF0000u);
    asm("cvt.rn.bf16x2.f32 %0, %1, %2;" : "=r"(lo.x) : "f"(l1), "f"(l0));
    asm("cvt.rn.bf16x2.f32 %0, %1, %2;" : "=r"(lo.y) : "f"(l3), "f"(l2));
}

// ---------------- init: zero accumulators + split/layout weights ----------------
__global__ void init_kernel(const float* __restrict__ WL,
                            const float* __restrict__ W1,
                            const float* __restrict__ W2) {
    const int gtid = blockIdx.x * 256 + threadIdx.x;
    const int n1 = NGRAPHS * NF;
    for (int i = gtid; i < n1; i += gridDim.x * 256) g_S[i] = 0.f;
    if (gtid < 2 * NF) { g_stat0[gtid] = 0.f; g_stat1[gtid] = 0.f; }
    if (gtid == 0) { g_sync0 = 0u; g_sync1 = 0u; }
    if (gtid < NF * NF) {
        int k = gtid >> 7, n = gtid & 127;
        uint32_t off = (uint32_t)k * 272 + (uint32_t)n * 2;
        float v; __nv_bfloat16 h, l;
        v = WL[gtid]; h = __float2bfloat16(v); l = __float2bfloat16(v - __bfloat162float(h));
        *(unsigned short*)((unsigned char*)g_wlhi + off) = __bfloat16_as_ushort(h);
        *(unsigned short*)((unsigned char*)g_wllo + off) = __bfloat16_as_ushort(l);
        v = W1[gtid]; h = __float2bfloat16(v); l = __float2bfloat16(v - __bfloat162float(h));
        *(unsigned short*)((unsigned char*)g_w1hi + off) = __bfloat16_as_ushort(h);
        *(unsigned short*)((unsigned char*)g_w1lo + off) = __bfloat16_as_ushort(l);
        v = W2[gtid]; h = __float2bfloat16(v); l = __float2bfloat16(v - __bfloat162float(h));
        *(unsigned short*)((unsigned char*)g_w2hi + off) = __bfloat16_as_ushort(h);
        *(unsigned short*)((unsigned char*)g_w2lo + off) = __bfloat16_as_ushort(l);
    }
}

// float4 lanes: 32 threads/row, 4 row-lanes, run-length accumulate per lane
__global__ void seg_sum_kernel(const float* __restrict__ x,
                               const int* __restrict__ batch, int M) {
    const int rg = threadIdx.x >> 5;
    const int c4 = threadIdx.x & 31;
    int r0 = blockIdx.x * 256;
    int rend = min(r0 + 256, M);
    float4 acc = make_float4(0.f, 0.f, 0.f, 0.f);
    int cur = -1;
    for (int r = r0 + rg; r < rend; r += 4) {
        int b = __ldg(&batch[r]);
        if (b != cur) {
            if (cur >= 0) {
                float* d = &g_S[(size_t)cur * NF + c4 * 4];
                atomicAdd(d + 0, acc.x); atomicAdd(d + 1, acc.y);
                atomicAdd(d + 2, acc.z); atomicAdd(d + 3, acc.w);
            }
            acc = make_float4(0.f, 0.f, 0.f, 0.f); cur = b;
        }
        float4 v = __ldg((const float4*)x + (size_t)r * 32 + c4);
        acc.x += v.x; acc.y += v.y; acc.z += v.z; acc.w += v.w;
    }
    if (cur >= 0) {
        float* d = &g_S[(size_t)cur * NF + c4 * 4];
        atomicAdd(d + 0, acc.x); atomicAdd(d + 1, acc.y);
        atomicAdd(d + 2, acc.z); atomicAdd(d + 3, acc.w);
    }
}

// ---------------- persistent HMMA GEMM, BM=64, 128 thr, 2 CTAs/SM ----------------
// 4 warps, 2(m)x2(n) grid, warp tile 32x64.
// MODE 0: C = Asrc @ W                                  (+ BN0 stats + bn-prep tail)
// MODE 1: C = (x + relu(P[batch]*sc+sh)) @ W + bias     (+ BN1 stats + bn-prep tail)
// MODE 2: C = relu(Asrc*sc + sh) @ W + bias
template <int MODE>
__global__ void __launch_bounds__(128, 2)
gemm_mma(const float* __restrict__ Asrc,
         const uint4* __restrict__ Whi_g, const uint4* __restrict__ Wlo_g,
         const float* __restrict__ bias,
         const float* __restrict__ Tm, const int* __restrict__ batch,
         const float* __restrict__ sc, const float* __restrict__ sh,
         float* __restrict__ C, float* __restrict__ stats,
         const float* __restrict__ gamma, const float* __restrict__ beta,
         float nrows, float* __restrict__ sc_out, float* __restrict__ sh_out,
         unsigned* __restrict__ sync_ctr, int M, int ntiles) {
    constexpr bool STATS = (MODE != 2);
    constexpr bool HASBIAS = (MODE != 0);

    extern __shared__ unsigned char sm[];
    float* psm = (float*)(sm + OFF_PRM);     // sc[128] @128, sh[128] @256
    const uint32_t sb = (uint32_t)__cvta_generic_to_shared(sm);

    const int tid = threadIdx.x;
    const int wid = tid >> 5, lane = tid & 31;
    const int tig = lane & 3, grp = lane >> 2;
    const int warp_m = wid >> 1, warp_n = wid & 1;   // 2x2 grid, 32x64 per warp

    if (MODE != 0 && tid < NF) {
        psm[128 + tid] = __ldg(&sc[tid]);
        psm[256 + tid] = __ldg(&sh[tid]);
    }
    {
        uint4* dh = (uint4*)(sm + OFF_WHI);
        uint4* dl = (uint4*)(sm + OFF_WLO);
        for (int i = tid; i < 2176; i += 128) {
            dh[i] = __ldg(&Whi_g[i]);
            dl[i] = __ldg(&Wlo_g[i]);
        }
    }
    __syncthreads();

    // per-lane BN params for convert (lane <-> column block fixed)
    float4 sc4, sh4;
    if (MODE != 0) {
        sc4 = ((const float4*)(psm + 128))[lane];
        sh4 = ((const float4*)(psm + 256))[lane];
    }

    float bias_r[8][2];
#pragma unroll
    for (int nt = 0; nt < 8; ++nt) {
        bias_r[nt][0] = HASBIAS ? __ldg(&bias[warp_n * 64 + nt * 8 + tig * 2]) : 0.f;
        bias_r[nt][1] = HASBIAS ? __ldg(&bias[warp_n * 64 + nt * 8 + tig * 2 + 1]) : 0.f;
    }

    float cs[8][2], cq[8][2];
    if (STATS) {
#pragma unroll
        for (int nt = 0; nt < 8; ++nt) { cs[nt][0] = cs[nt][1] = 0.f; cq[nt][0] = cq[nt][1] = 0.f; }
    }

    const int lrow = lane & 15, lsel = lane >> 4;
    unsigned char* Ah = sm + OFF_AHI;
    unsigned char* Al = sm + OFF_ALO;

    for (int tile = blockIdx.x; tile < ntiles; tile += gridDim.x) {
        // ---- convert: warp handles rows [wid*16, wid*16+16), lane = float4 col ----
        {
            int crow0 = wid * 16;
            // depth-2 register pipeline on gmem loads
            float4 xc, tc, xn, tn;
            {
                int rg = tile * BM + crow0;
                int rc = min(rg, M - 1);
                xc = __ldg((const float4*)(Asrc + (size_t)rc * NF) + lane);
                if (MODE == 1)
                    tc = __ldg((const float4*)(Tm + (size_t)__ldg(&batch[rc]) * NF) + lane);
            }
#pragma unroll
            for (int i = 0; i < 16; ++i) {
                int crow = crow0 + i;
                int rg = tile * BM + crow;
                bool valid = rg < M;
                if (i < 15) {
                    int rgn = rg + 1;
                    int rc = min(rgn, M - 1);
                    xn = __ldg((const float4*)(Asrc + (size_t)rc * NF) + lane);
                    if (MODE == 1)
                        tn = __ldg((const float4*)(Tm + (size_t)__ldg(&batch[rc]) * NF) + lane);
                }
                float4 v = xc;
                if (MODE == 1) {
                    v.x += fmaxf(fmaf(tc.x, sc4.x, sh4.x), 0.f);
                    v.y += fmaxf(fmaf(tc.y, sc4.y, sh4.y), 0.f);
                    v.z += fmaxf(fmaf(tc.z, sc4.z, sh4.z), 0.f);
                    v.w += fmaxf(fmaf(tc.w, sc4.w, sh4.w), 0.f);
                } else if (MODE == 2) {
                    v.x = fmaxf(fmaf(v.x, sc4.x, sh4.x), 0.f);
                    v.y = fmaxf(fmaf(v.y, sc4.y, sh4.y), 0.f);
                    v.z = fmaxf(fmaf(v.z, sc4.z, sh4.z), 0.f);
                    v.w = fmaxf(fmaf(v.w, sc4.w, sh4.w), 0.f);
                }
                if (!valid) v = make_float4(0.f, 0.f, 0.f, 0.f);
                uint2 hi, lo;
                split4(v, hi, lo);
                uint32_t off = (uint32_t)crow * 272 + (uint32_t)lane * 8;
                *(uint2*)(Ah + off) = hi;
                *(uint2*)(Al + off) = lo;
                xc = xn; tc = tn;
            }
        }
        __syncthreads();

        // ---- HMMA mainloop: 3-chain bf16 split, 32x64 microtile/warp ----
        float acc[2][8][4];
#pragma unroll
        for (int mt = 0; mt < 2; ++mt)
#pragma unroll
            for (int nt = 0; nt < 8; ++nt)
#pragma unroll
                for (int e = 0; e < 4; ++e) acc[mt][nt][e] = 0.f;

#pragma unroll
        for (int kt = 0; kt < 8; ++kt) {
            const int k0 = kt * 16;
            uint32_t ahi[2][4], alo[2][4], whi[4][4], wlo[4][4];
#pragma unroll
            for (int mt = 0; mt < 2; ++mt) {
                int r = warp_m * 32 + mt * 16 + lrow;
                uint32_t a = sb + OFF_AHI + (uint32_t)r * 272 + (uint32_t)(k0 + lsel * 8) * 2;
                ldsm_x4(ahi[mt], a);
                ldsm_x4(alo[mt], a + (OFF_ALO - OFF_AHI));
            }
#pragma unroll
            for (int nb = 0; nb < 4; ++nb) {
                int n0 = warp_n * 64 + nb * 16;
                uint32_t a = sb + OFF_WHI + (uint32_t)(k0 + lrow) * 272 + (uint32_t)(n0 + lsel * 8) * 2;
                ldsm_x4_t(whi[nb], a);
                ldsm_x4_t(wlo[nb], a + (OFF_WLO - OFF_WHI));
            }
#pragma unroll
            for (int mt = 0; mt < 2; ++mt)
#pragma unroll
                for (int nt = 0; nt < 8; ++nt) {
                    const uint32_t* bh = &whi[nt >> 1][(nt & 1) * 2];
                    const uint32_t* bl = &wlo[nt >> 1][(nt & 1) * 2];
                    mma_bf16(acc[mt][nt], ahi[mt], bh);
                    mma_bf16(acc[mt][nt], ahi[mt], bl);
                    mma_bf16(acc[mt][nt], alo[mt], bh);
                }
        }

        // ---- epilogue: bias, store, fused stats ----
#pragma unroll
        for (int mt = 0; mt < 2; ++mt) {
            int r0 = tile * BM + warp_m * 32 + mt * 16 + grp;
            int r1 = r0 + 8;
            bool v0 = r0 < M, v1 = r1 < M;
            float* p0 = C + (size_t)r0 * NF + warp_n * 64 + tig * 2;
            float* p1 = C + (size_t)r1 * NF + warp_n * 64 + tig * 2;
#pragma unroll
            for (int nt = 0; nt < 8; ++nt) {
                float c0 = acc[mt][nt][0] + bias_r[nt][0];
                float c1 = acc[mt][nt][1] + bias_r[nt][1];
                float c2 = acc[mt][nt][2] + bias_r[nt][0];
                float c3 = acc[mt][nt][3] + bias_r[nt][1];
                if (v0) {
                    *(float2*)(p0 + nt * 8) = make_float2(c0, c1);
                    if (STATS) { cs[nt][0] += c0; cs[nt][1] += c1; cq[nt][0] += c0 * c0; cq[nt][1] += c1 * c1; }
                }
                if (v1) {
                    *(float2*)(p1 + nt * 8) = make_float2(c2, c3);
                    if (STATS) { cs[nt][0] += c2; cs[nt][1] += c3; cq[nt][0] += c2 * c2; cq[nt][1] += c3 * c3; }
                }
            }
        }
        __syncthreads();   // all reads of A done before next convert overwrites
    }

    // ---- stats flush + last-block bn-prep ----
    if (STATS) {
        float* cs_sm = (float*)(sm + OFF_AHI);     // [4][64]
        float* cq_sm = cs_sm + 256;
#pragma unroll
        for (int nt = 0; nt < 8; ++nt)
#pragma unroll
            for (int par = 0; par < 2; ++par) {
                float s = cs[nt][par], q = cq[nt][par];
#pragma unroll
                for (int msk = 16; msk >= 4; msk >>= 1) {
                    s += __shfl_xor_sync(0xFFFFFFFFu, s, msk);
                    q += __shfl_xor_sync(0xFFFFFFFFu, q, msk);
                }
                if (lane < 4) {
                    cs_sm[wid * 64 + nt * 8 + tig * 2 + par] = s;
                    cq_sm[wid * 64 + nt * 8 + tig * 2 + par] = q;
                }
            }
        __syncthreads();
        {
            int col = tid;                 // 128 threads = 128 columns
            int wn = col >> 6, cl = col & 63;
            atomicAdd(&stats[col],      cs_sm[wn * 64 + cl] + cs_sm[(wn + 2) * 64 + cl]);
            atomicAdd(&stats[NF + col], cq_sm[wn * 64 + cl] + cq_sm[(wn + 2) * 64 + cl]);
        }

        __shared__ unsigned last_f;
        __threadfence();
        __syncthreads();
        if (tid == 0) last_f = (atomicAdd(sync_ctr, 1u) == (unsigned)(gridDim.x - 1)) ? 1u : 0u;
        __syncthreads();
        if (last_f) {
            float su = atomicAdd(&stats[tid], 0.f);
            float sq = atomicAdd(&stats[NF + tid], 0.f);
            float mu = su / nrows;
            float var = sq / nrows - mu * mu;
            float s = rsqrtf(var + EPSBN) * __ldg(&gamma[tid]);
            sc_out[tid] = s;
            sh_out[tid] = __ldg(&beta[tid]) - mu * s;
        }
    }
}

// ---------------- launcher ----------------
extern "C" void kernel_launch(void* const* d_in, const int* in_sizes, int n_in,
                              void* d_out, int out_size) {
    const float* x     = (const float*)d_in[0];
    const int*   batch = (const int*)d_in[3];
    const float* W_lin = (const float*)d_in[4];
    const float* bn_g  = (const float*)d_in[5];
    const float* bn_b  = (const float*)d_in[6];
    const float* W1    = (const float*)d_in[7];
    const float* b1    = (const float*)d_in[8];
    const float* bn1_g = (const float*)d_in[9];
    const float* bn1_b = (const float*)d_in[10];
    const float* W2    = (const float*)d_in[11];
    const float* b2    = (const float*)d_in[12];
    float*       out   = (float*)d_out;

    const int M = in_sizes[0] / NF;   // 500000
    const int ntiles_big = (M + BM - 1) / BM;
    const int ntiles_sml = (NGRAPHS + BM - 1) / BM;   // 157

    float *pS, *pP, *pH1, *pstat0, *psc0, *psh0, *pstat1, *psc1, *psh1;
    cudaGetSymbolAddress((void**)&pS, g_S);
    cudaGetSymbolAddress((void**)&pP, g_P);
    cudaGetSymbolAddress((void**)&pH1, g_H1);
    cudaGetSymbolAddress((void**)&pstat0, g_stat0);
    cudaGetSymbolAddress((void**)&psc0, g_sc0);
    cudaGetSymbolAddress((void**)&psh0, g_sh0);
    cudaGetSymbolAddress((void**)&pstat1, g_stat1);
    cudaGetSymbolAddress((void**)&psc1, g_sc1);
    cudaGetSymbolAddress((void**)&psh1, g_sh1);
    unsigned *psync0, *psync1;
    cudaGetSymbolAddress((void**)&psync0, g_sync0);
    cudaGetSymbolAddress((void**)&psync1, g_sync1);
    uint4 *pwlh, *pwll, *pw1h, *pw1l, *pw2h, *pw2l;
    cudaGetSymbolAddress((void**)&pwlh, g_wlhi);
    cudaGetSymbolAddress((void**)&pwll, g_wllo);
    cudaGetSymbolAddress((void**)&pw1h, g_w1hi);
    cudaGetSymbolAddress((void**)&pw1l, g_w1lo);
    cudaGetSymbolAddress((void**)&pw2h, g_w2hi);
    cudaGetSymbolAddress((void**)&pw2l, g_w2lo);

    int dev = 0, nsm = 148;
    cudaGetDevice(&dev);
    cudaDeviceGetAttribute(&nsm, cudaDevAttrMultiProcessorCount, dev);
    const int grid_big = 2 * nsm;
    const int grid_sml = (grid_big < ntiles_sml) ? grid_big : ntiles_sml;

    cudaFuncSetAttribute(gemm_mma<0>, cudaFuncAttributeMaxDynamicSharedMemorySize, SMEM_MMA);
    cudaFuncSetAttribute(gemm_mma<1>, cudaFuncAttributeMaxDynamicSharedMemorySize, SMEM_MMA);
    cudaFuncSetAttribute(gemm_mma<2>, cudaFuncAttributeMaxDynamicSharedMemorySize, SMEM_MMA);

    // (1) init
    init_kernel<<<2500, 256>>>(W_lin, W1, W2);
    // (2) segment sum
    seg_sum_kernel<<<(M + 255) / 256, 128>>>(x, batch, M);
    // (3) P = S @ W_lin  (+ BN0 stats + bn-prep tail)
    gemm_mma<0><<<grid_sml, 128, SMEM_MMA>>>(pS, pwlh, pwll, nullptr, nullptr, nullptr,
                                             nullptr, nullptr, pP, pstat0,
                                             bn_g, bn_b, (float)NGRAPHS, psc0, psh0,
                                             psync0, NGRAPHS, ntiles_sml);
    // (4) H1 = (x + relu(BN0(P))[batch]) @ W1 + b1  (+ BN1 stats + bn-prep tail)
    gemm_mma<1><<<grid_big, 128, SMEM_MMA>>>(x, pw1h, pw1l, b1, pP, batch,
                                             psc0, psh0, pH1, pstat1,
                                             bn1_g, bn1_b, (float)M, psc1, psh1,
                                             psync1, M, ntiles_big);
    // (5) out = relu(BN1(H1)) @ W2 + b2
    gemm_mma<2><<<grid_big, 128, SMEM_MMA>>>(pH1, pw2h, pw2l, b2, nullptr, nullptr,
                                             psc1, psh1, out, nullptr,
                                             nullptr, nullptr, 0.f, nullptr, nullptr,
                                             nullptr, M, ntiles_big);
}